// round 6
// baseline (speedup 1.0000x reference)
#include <cuda_runtime.h>
#include <math.h>

// Shape fixed by reference: x,y = [16, 3, 512, 512] f32
#define BATCH   16
#define HDIM    512
#define WDIM    512
#define RSTRIP  16                    // output rows per warp
#define STRIPS  (HDIM / RSTRIP)       // 32
#define WPB     8                     // warps per block (8 adjacent strips)
#define SGROUPS (STRIPS / WPB)        // 4
#define COLT    4                     // column tiles of 128
#define NBLOCKS (BATCH * COLT * SGROUPS)  // 256
#define THREADS (WPB * 32)            // 256
#define ROWSIN  (RSTRIP + 6)          // 22 input rows per warp
#define EPSV    1e-6f

__device__ float        g_partials[NBLOCKS];
__device__ unsigned int g_count;     // zero-init at load; reset by last block

__global__ __launch_bounds__(THREADS, 2) void charb_kernel(
    const float* __restrict__ x, const float* __restrict__ y,
    float* __restrict__ out)
{
    __shared__ float warpsum[WPB];
    __shared__ bool  isLast;

    const int tid  = threadIdx.x;
    const int wid  = tid >> 5;
    const int lane = tid & 31;

    const int blk = blockIdx.x;
    const int b   = blk >> 4;          // batch
    const int rem = blk & 15;
    const int ct  = rem >> 2;          // column tile 0..3
    const int sg  = rem & 3;           // strip group 0..3

    const int strip = sg * WPB + wid;  // 0..31 (adjacent strips in one block)
    const int h0    = strip * RSTRIP;
    const int c0    = ct * 128 + lane * 4;

    const bool isL = (lane == 0);
    const bool isR = (lane == 31);
    const int  hc  = isL ? (c0 - 4) : (c0 + 4);   // halo float4 col (lanes 0/31)
    const bool haloLane = (isL && hc >= 0) || (isR && hc < WDIM);

    const size_t plane = (size_t)HDIM * WDIM;
    const float* xb = x + (size_t)b * 3 * plane;
    const float* yb = y + (size_t)b * 3 * plane;

    const float4 z4 = make_float4(0.f, 0.f, 0.f, 0.f);

    // pipelined raw loads for one row
    float4 m0 = z4, m1 = z4, m2 = z4, n0 = z4, n1 = z4, n2 = z4;
    float4 hx0 = z4, hx1 = z4, hx2 = z4, hy0 = z4, hy1 = z4, hy2 = z4;

    {   // prologue: load row i = 0  (r = h0 - 3)
        const int r = h0 - 3;
        if (r >= 0) {                          // r < HDIM always here
            const float* xp = xb + (size_t)r * WDIM + c0;
            const float* yp = yb + (size_t)r * WDIM + c0;
            m0 = *(const float4*)(xp);
            m1 = *(const float4*)(xp + plane);
            m2 = *(const float4*)(xp + 2 * plane);
            n0 = *(const float4*)(yp);
            n1 = *(const float4*)(yp + plane);
            n2 = *(const float4*)(yp + 2 * plane);
            if (haloLane) {
                const float* hxp = xb + (size_t)r * WDIM + hc;
                const float* hyp = yb + (size_t)r * WDIM + hc;
                hx0 = *(const float4*)(hxp);
                hx1 = *(const float4*)(hxp + plane);
                hx2 = *(const float4*)(hxp + 2 * plane);
                hy0 = *(const float4*)(hyp);
                hy1 = *(const float4*)(hyp + plane);
                hy2 = *(const float4*)(hyp + 2 * plane);
            }
        }
    }

    // vertical ring: r0..r5 hold the 6 previous h-sum rows; vs = running 7-row sum
    float4 r0 = z4, r1 = z4, r2 = z4, r3 = z4, r4 = z4, r5 = z4;
    float4 vs = z4;
    float  acc = 0.f;

    #pragma unroll 1
    for (int i = 0; i < ROWSIN; ++i) {
        // consume current loads: channel-summed diff (+ halo diff on lanes 0/31)
        float4 d, dh;
        d.x = (m0.x - n0.x) + (m1.x - n1.x) + (m2.x - n2.x);
        d.y = (m0.y - n0.y) + (m1.y - n1.y) + (m2.y - n2.y);
        d.z = (m0.z - n0.z) + (m1.z - n1.z) + (m2.z - n2.z);
        d.w = (m0.w - n0.w) + (m1.w - n1.w) + (m2.w - n2.w);
        dh.x = (hx0.x - hy0.x) + (hx1.x - hy1.x) + (hx2.x - hy2.x);
        dh.y = (hx0.y - hy0.y) + (hx1.y - hy1.y) + (hx2.y - hy2.y);
        dh.z = (hx0.z - hy0.z) + (hx1.z - hy1.z) + (hx2.z - hy2.z);
        dh.w = (hx0.w - hy0.w) + (hx1.w - hy1.w) + (hx2.w - hy2.w);

        // prefetch row i+1 (registers are dead now; no barrier between issue & use)
        {
            const int nr  = h0 - 3 + i + 1;
            const bool nv = (i + 1 < ROWSIN) && (nr >= 0) && (nr < HDIM);
            m0 = z4; m1 = z4; m2 = z4; n0 = z4; n1 = z4; n2 = z4;
            hx0 = z4; hx1 = z4; hx2 = z4; hy0 = z4; hy1 = z4; hy2 = z4;
            if (nv) {
                const float* xp = xb + (size_t)nr * WDIM + c0;
                const float* yp = yb + (size_t)nr * WDIM + c0;
                m0 = *(const float4*)(xp);
                m1 = *(const float4*)(xp + plane);
                m2 = *(const float4*)(xp + 2 * plane);
                n0 = *(const float4*)(yp);
                n1 = *(const float4*)(yp + plane);
                n2 = *(const float4*)(yp + 2 * plane);
                if (haloLane) {
                    const float* hxp = xb + (size_t)nr * WDIM + hc;
                    const float* hyp = yb + (size_t)nr * WDIM + hc;
                    hx0 = *(const float4*)(hxp);
                    hx1 = *(const float4*)(hxp + plane);
                    hx2 = *(const float4*)(hxp + 2 * plane);
                    hy0 = *(const float4*)(hyp);
                    hy1 = *(const float4*)(hyp + plane);
                    hy2 = *(const float4*)(hyp + 2 * plane);
                }
            }
        }

        // horizontal neighbors via shuffles (no smem, no barrier)
        float py = __shfl_up_sync(0xffffffffu, d.y, 1);
        float pz = __shfl_up_sync(0xffffffffu, d.z, 1);
        float pw = __shfl_up_sync(0xffffffffu, d.w, 1);
        float nx = __shfl_down_sync(0xffffffffu, d.x, 1);
        float ny = __shfl_down_sync(0xffffffffu, d.y, 1);
        float nz = __shfl_down_sync(0xffffffffu, d.z, 1);
        if (isL) { py = dh.y; pz = dh.z; pw = dh.w; }
        if (isR) { nx = dh.x; ny = dh.y; nz = dh.z; }

        // horizontal 7-tap sums for this lane's 4 columns
        float4 s;
        s.x = ((py + pz) + (pw + d.x)) + ((d.y + d.z) + d.w);
        s.y = s.x - py + nx;
        s.z = s.y - pz + ny;
        s.w = s.z - pw + nz;

        // vertical running 7-row sum + Charbonnier
        vs.x += s.x; vs.y += s.y; vs.z += s.z; vs.w += s.w;
        if (i >= 6) {
            const float inv = 1.f / 49.f;
            const float v0 = vs.x * inv, v1 = vs.y * inv;
            const float v2 = vs.z * inv, v3 = vs.w * inv;
            acc += (sqrtf(v0 * v0 + EPSV) + sqrtf(v1 * v1 + EPSV))
                 + (sqrtf(v2 * v2 + EPSV) + sqrtf(v3 * v3 + EPSV));
            vs.x -= r0.x; vs.y -= r0.y; vs.z -= r0.z; vs.w -= r0.w;
        }
        r0 = r1; r1 = r2; r2 = r3; r3 = r4; r4 = r5; r5 = s;
    }

    // warp reduce
    #pragma unroll
    for (int off = 16; off; off >>= 1) acc += __shfl_xor_sync(0xffffffffu, acc, off);
    if (lane == 0) warpsum[wid] = acc;
    __syncthreads();

    if (tid < 32) {
        float v = (tid < WPB) ? warpsum[tid] : 0.f;
        #pragma unroll
        for (int off = 4; off; off >>= 1) v += __shfl_xor_sync(0xffffffffu, v, off);
        if (tid == 0) {
            g_partials[blk] = v;
            __threadfence();
            const unsigned int t = atomicAdd(&g_count, 1u);
            isLast = (t == NBLOCKS - 1);
        }
    }
    __syncthreads();

    // last-arriving block folds the 256 partials -> scalar (deterministic order)
    if (isLast) {
        __threadfence();
        float v = (tid < NBLOCKS) ? g_partials[tid] : 0.f;
        #pragma unroll
        for (int off = 16; off; off >>= 1) v += __shfl_xor_sync(0xffffffffu, v, off);
        if ((tid & 31) == 0) warpsum[tid >> 5] = v;
        __syncthreads();
        if (tid < 32) {
            float v2 = (tid < WPB) ? warpsum[tid] : 0.f;
            #pragma unroll
            for (int off = 4; off; off >>= 1) v2 += __shfl_xor_sync(0xffffffffu, v2, off);
            if (tid == 0) {
                out[0]  = v2 / (float)((size_t)BATCH * HDIM * WDIM);
                g_count = 0u;
            }
        }
    }
}

extern "C" void kernel_launch(void* const* d_in, const int* in_sizes, int n_in,
                              void* d_out, int out_size)
{
    (void)in_sizes; (void)n_in; (void)out_size;
    const float* x = (const float*)d_in[0];
    const float* y = (const float*)d_in[1];
    float* out = (float*)d_out;

    charb_kernel<<<NBLOCKS, THREADS>>>(x, y, out);
}